// round 1
// baseline (speedup 1.0000x reference)
#include <cuda_runtime.h>
#include <cuda_bf16.h>

#define N_NODES 8192
#define FIN     512
#define FOUT    256

// Scratch (device globals: the sanctioned alloc-free scratch mechanism)
__device__ float g_h[(size_t)N_NODES * FOUT];     // 8 MB, h = x @ W
__device__ float g_s[2 * N_NODES];                // s_src | s_dst

// mish(u) = u * tanh(softplus(u)) = u * (t^2 + 2t) / (t^2 + 2t + 2), t = e^u
__device__ __forceinline__ float fast_mish(float u) {
    if (u > 30.f) return u;          // tanh(softplus(u)) == 1.0f in fp32
    float t = __expf(u);
    float v = t * (t + 2.f);
    return u * __fdividef(v, v + 2.f);
}

// ---------------------------------------------------------------------------
// Kernel 1: h = x @ W   (8192x512 @ 512x256)
// BM=64, BN=64, BK=16, 256 threads, 4x4 microtile
// ---------------------------------------------------------------------------
__global__ __launch_bounds__(256) void k_sgemm_xw(
    const float* __restrict__ X, const float* __restrict__ W)
{
    __shared__ float As[16][64];   // [k][m]
    __shared__ float Bs[16][64];   // [k][n]

    const int bn = blockIdx.x * 64;
    const int bm = blockIdx.y * 64;
    const int tid = threadIdx.x;
    const int tx = tid & 15;       // 16 col-threads
    const int ty = tid >> 4;       // 16 row-threads

    float acc[4][4];
#pragma unroll
    for (int r = 0; r < 4; r++)
#pragma unroll
        for (int c = 0; c < 4; c++) acc[r][c] = 0.f;

    for (int k0 = 0; k0 < FIN; k0 += 16) {
#pragma unroll
        for (int i = tid; i < 1024; i += 256) {
            int m = i >> 4, k = i & 15;
            As[k][m] = X[(size_t)(bm + m) * FIN + k0 + k];
        }
#pragma unroll
        for (int i = tid; i < 1024; i += 256) {
            int k = i >> 6, n = i & 63;
            Bs[k][n] = W[(size_t)(k0 + k) * FOUT + bn + n];
        }
        __syncthreads();
#pragma unroll
        for (int k = 0; k < 16; k++) {
            float4 a4 = *(const float4*)&As[k][ty * 4];
            float4 b4 = *(const float4*)&Bs[k][tx * 4];
            float a[4] = {a4.x, a4.y, a4.z, a4.w};
            float b[4] = {b4.x, b4.y, b4.z, b4.w};
#pragma unroll
            for (int r = 0; r < 4; r++)
#pragma unroll
                for (int c = 0; c < 4; c++) acc[r][c] = fmaf(a[r], b[c], acc[r][c]);
        }
        __syncthreads();
    }
#pragma unroll
    for (int r = 0; r < 4; r++) {
        float4 o = {acc[r][0], acc[r][1], acc[r][2], acc[r][3]};
        *(float4*)&g_h[(size_t)(bm + ty * 4 + r) * FOUT + bn + tx * 4] = o;
    }
}

// ---------------------------------------------------------------------------
// Kernel 2: s_src[i] = h[i,:] . a[:256],  s_dst[i] = h[i,:] . a[256:]
// one warp per row
// ---------------------------------------------------------------------------
__global__ __launch_bounds__(256) void k_scores(const float* __restrict__ A)
{
    const int row  = blockIdx.x * 8 + (threadIdx.x >> 5);
    const int lane = threadIdx.x & 31;

    const float4* h4  = (const float4*)(g_h + (size_t)row * FOUT);
    const float4* a14 = (const float4*)A;
    const float4* a24 = (const float4*)(A + FOUT);

    float s1 = 0.f, s2 = 0.f;
#pragma unroll
    for (int i = 0; i < 2; i++) {
        int idx = lane + i * 32;         // float4 index 0..63
        float4 h  = h4[idx];
        float4 a1 = a14[idx];
        float4 a2 = a24[idx];
        s1 += h.x * a1.x + h.y * a1.y + h.z * a1.z + h.w * a1.w;
        s2 += h.x * a2.x + h.y * a2.y + h.z * a2.z + h.w * a2.w;
    }
#pragma unroll
    for (int off = 16; off; off >>= 1) {
        s1 += __shfl_down_sync(0xffffffffu, s1, off);
        s2 += __shfl_down_sync(0xffffffffu, s2, off);
    }
    if (lane == 0) {
        g_s[row]           = s1;
        g_s[N_NODES + row] = s2;
    }
}

// ---------------------------------------------------------------------------
// Kernel 3: fused masked-softmax attention + aggregation + output mish.
// out[i,:] = mish( (sum_j w_ij * h[j,:]) / (sum_j w_ij) ),
//   w_ij = (adj[i][j] > 0) ? exp(mish(s_src[i] + s_dst[j])) : 0
// No max-subtraction needed: |s_src+s_dst| <= ~14, exp() safe in fp32.
// BM=64 rows/CTA, BN=256 (full width), BK=16, 256 threads, 8x8 microtile.
// ---------------------------------------------------------------------------
#define BM 64
#define BK 16

__global__ __launch_bounds__(256) void k_gat_attn(
    const int* __restrict__ adj, float* __restrict__ out)
{
    __shared__ float Bs[BK][FOUT];      // 16 KB: h tile [k][n]
    __shared__ float Ws[BK][BM];        //  4 KB: weights tile [k][m]
    __shared__ float ssrc_s[BM];
    __shared__ float rsum_s[4][BM];

    const int row0 = blockIdx.x * BM;
    const int tid  = threadIdx.x;

    // w-generation mapping: 4 threads per row, 4 consecutive k each
    const int wr  = tid & 63;
    const int wkg = tid >> 6;           // 0..3

    // FMA mapping: 32 col-threads x 8 row-threads, 8x8 microtile
    const int tx = tid & 31;
    const int ty = tid >> 5;

    if (tid < BM) ssrc_s[tid] = g_s[row0 + tid];
    __syncthreads();
    const float my_ssrc = ssrc_s[wr];
    const float* __restrict__ sdst = g_s + N_NODES;

    float acc[8][8];
#pragma unroll
    for (int r = 0; r < 8; r++)
#pragma unroll
        for (int c = 0; c < 8; c++) acc[r][c] = 0.f;
    float psum = 0.f;

    const size_t adj_row = (size_t)(row0 + wr) * N_NODES;

    for (int k0 = 0; k0 < N_NODES; k0 += BK) {
        // --- generate w tile (4 elements per thread) ---
        {
            int4   av  = *(const int4*)(adj + adj_row + k0 + wkg * 4);
            float4 sdv = *(const float4*)(sdst + k0 + wkg * 4);
            float w0 = (av.x > 0) ? __expf(fast_mish(my_ssrc + sdv.x)) : 0.f;
            float w1 = (av.y > 0) ? __expf(fast_mish(my_ssrc + sdv.y)) : 0.f;
            float w2 = (av.z > 0) ? __expf(fast_mish(my_ssrc + sdv.z)) : 0.f;
            float w3 = (av.w > 0) ? __expf(fast_mish(my_ssrc + sdv.w)) : 0.f;
            Ws[wkg * 4 + 0][wr] = w0;
            Ws[wkg * 4 + 1][wr] = w1;
            Ws[wkg * 4 + 2][wr] = w2;
            Ws[wkg * 4 + 3][wr] = w3;
            psum += (w0 + w1) + (w2 + w3);
        }
        // --- load h tile: 16 rows x 256 cols contiguous -> 1024 float4 ---
        {
            const float4* hsrc = (const float4*)(g_h + (size_t)k0 * FOUT);
            float4* bdst = (float4*)&Bs[0][0];
#pragma unroll
            for (int i = tid; i < 1024; i += 256) bdst[i] = hsrc[i];
        }
        __syncthreads();

        // --- FMA: acc += w[k][m] * h[k][n] ---
#pragma unroll
        for (int kk = 0; kk < BK; kk++) {
            float4 w0 = *(const float4*)&Ws[kk][ty * 8];
            float4 w1 = *(const float4*)&Ws[kk][ty * 8 + 4];
            float4 b0 = *(const float4*)&Bs[kk][tx * 8];
            float4 b1 = *(const float4*)&Bs[kk][tx * 8 + 4];
            float wv[8] = {w0.x, w0.y, w0.z, w0.w, w1.x, w1.y, w1.z, w1.w};
            float bv[8] = {b0.x, b0.y, b0.z, b0.w, b1.x, b1.y, b1.z, b1.w};
#pragma unroll
            for (int r = 0; r < 8; r++)
#pragma unroll
                for (int c = 0; c < 8; c++)
                    acc[r][c] = fmaf(wv[r], bv[c], acc[r][c]);
        }
        __syncthreads();
    }

    // --- row-sum reduction (no atomics: 4 partials per row) ---
    rsum_s[wkg][wr] = psum;
    __syncthreads();
    if (tid < BM) {
        rsum_s[0][tid] = (rsum_s[0][tid] + rsum_s[1][tid]) +
                         (rsum_s[2][tid] + rsum_s[3][tid]);
    }
    __syncthreads();

    // --- epilogue: normalize + mish + store ---
#pragma unroll
    for (int r = 0; r < 8; r++) {
        float inv = __fdividef(1.f, rsum_s[0][ty * 8 + r]);
        float4 o0, o1;
        o0.x = fast_mish(acc[r][0] * inv);
        o0.y = fast_mish(acc[r][1] * inv);
        o0.z = fast_mish(acc[r][2] * inv);
        o0.w = fast_mish(acc[r][3] * inv);
        o1.x = fast_mish(acc[r][4] * inv);
        o1.y = fast_mish(acc[r][5] * inv);
        o1.z = fast_mish(acc[r][6] * inv);
        o1.w = fast_mish(acc[r][7] * inv);
        size_t base = (size_t)(row0 + ty * 8 + r) * FOUT + tx * 8;
        *(float4*)&out[base]     = o0;
        *(float4*)&out[base + 4] = o1;
    }
}

// ---------------------------------------------------------------------------
extern "C" void kernel_launch(void* const* d_in, const int* in_sizes, int n_in,
                              void* d_out, int out_size)
{
    const float* x   = (const float*)d_in[0];   // [8192, 512]
    const int*   adj = (const int*)  d_in[1];   // [8192, 8192]
    const float* w   = (const float*)d_in[2];   // [512, 256]
    const float* a   = (const float*)d_in[3];   // [512, 1]
    float* out = (float*)d_out;                 // [8192, 256]

    k_sgemm_xw<<<dim3(FOUT / 64, N_NODES / 64), 256>>>(x, w);
    k_scores<<<N_NODES / 8, 256>>>(a);
    k_gat_attn<<<N_NODES / BM, 256>>>(adj, out);
}

// round 3
// speedup vs baseline: 1.8223x; 1.8223x over previous
#include <cuda_runtime.h>
#include <cuda_bf16.h>
#include <cstdint>

#define N_NODES 8192
#define FIN     512
#define FOUT    256
#define NSPLIT  2
#define KHALF   (N_NODES / NSPLIT)   // 4096
#define BKC     64                   // K-chunk (64 j per mainloop iter)
#define NCHUNK  (KHALF / BKC)        // 64

// ---------------------------------------------------------------------------
// Device scratch (__device__ globals: the sanctioned alloc-free mechanism)
// ---------------------------------------------------------------------------
__device__ float g_h[(size_t)N_NODES * FOUT];              // 8 MB   h = x@W
__device__ float g_s[2 * N_NODES];                         // s_src | s_dst
__device__ __nv_bfloat16 g_hT_hi[(size_t)FOUT * N_NODES];  // 4 MB   h^T hi bf16
__device__ __nv_bfloat16 g_hT_lo[(size_t)FOUT * N_NODES];  // 4 MB   h^T residual
__device__ float g_pnum[(size_t)NSPLIT * N_NODES * FOUT];  // 16 MB  partial numer
__device__ float g_pden[NSPLIT * N_NODES];                 // partial denom

// mish(u) = u * tanh(softplus(u)) = u*(t^2+2t)/(t^2+2t+2), t=e^u
__device__ __forceinline__ float fast_mish(float u) {
    if (u > 30.f) return u;
    float t = __expf(u);
    float v = t * (t + 2.f);
    return u * __fdividef(v, v + 2.f);
}

__device__ __forceinline__ uint32_t smem_u32(const void* p) {
    uint32_t a;
    asm("{ .reg .u64 t; cvta.to.shared.u64 t, %1; cvt.u32.u64 %0, t; }" : "=r"(a) : "l"(p));
    return a;
}
__device__ __forceinline__ uint32_t pack_bf16(float a, float b) {
    return (uint32_t)__bfloat16_as_ushort(__float2bfloat16(a)) |
           ((uint32_t)__bfloat16_as_ushort(__float2bfloat16(b)) << 16);
}
#define SW128(x) ((x) ^ (((x) >> 3) & 0x70))

// ---- baseline-PTX tensor ops (valid on compute_103: sm_80-era) -------------
__device__ __forceinline__ void ldsm4(uint32_t* r, uint32_t addr) {
    asm volatile("ldmatrix.sync.aligned.m8n8.x4.shared.b16 {%0,%1,%2,%3}, [%4];"
                 : "=r"(r[0]), "=r"(r[1]), "=r"(r[2]), "=r"(r[3]) : "r"(addr));
}
__device__ __forceinline__ void mma_bf16(float* d, const uint32_t* a,
                                         uint32_t b0, uint32_t b1) {
    asm volatile("mma.sync.aligned.m16n8k16.row.col.f32.bf16.bf16.f32 "
                 "{%0,%1,%2,%3}, {%4,%5,%6,%7}, {%8,%9}, {%0,%1,%2,%3};"
                 : "+f"(d[0]), "+f"(d[1]), "+f"(d[2]), "+f"(d[3])
                 : "r"(a[0]), "r"(a[1]), "r"(a[2]), "r"(a[3]), "r"(b0), "r"(b1));
}
__device__ __forceinline__ void cpa16(uint32_t s, const void* g) {
    asm volatile("cp.async.cg.shared.global [%0], [%1], 16;" :: "r"(s), "l"(g));
}
#define CPA_COMMIT() asm volatile("cp.async.commit_group;" ::: "memory")
#define CPA_WAIT(n)  asm volatile("cp.async.wait_group %0;" :: "n"(n) : "memory")

// ---------------------------------------------------------------------------
// Kernel 1: h = x @ W  (FFMA SGEMM, 101us — optimize later)
// ---------------------------------------------------------------------------
__global__ __launch_bounds__(256) void k_sgemm_xw(
    const float* __restrict__ X, const float* __restrict__ W)
{
    __shared__ float As[16][64];
    __shared__ float Bs[16][64];
    const int bn = blockIdx.x * 64, bm = blockIdx.y * 64;
    const int tid = threadIdx.x, tx = tid & 15, ty = tid >> 4;
    float acc[4][4];
#pragma unroll
    for (int r = 0; r < 4; r++)
#pragma unroll
        for (int c = 0; c < 4; c++) acc[r][c] = 0.f;
    for (int k0 = 0; k0 < FIN; k0 += 16) {
#pragma unroll
        for (int i = tid; i < 1024; i += 256) {
            int m = i >> 4, k = i & 15;
            As[k][m] = X[(size_t)(bm + m) * FIN + k0 + k];
        }
#pragma unroll
        for (int i = tid; i < 1024; i += 256) {
            int k = i >> 6, n = i & 63;
            Bs[k][n] = W[(size_t)(k0 + k) * FOUT + bn + n];
        }
        __syncthreads();
#pragma unroll
        for (int k = 0; k < 16; k++) {
            float4 a4 = *(const float4*)&As[k][ty * 4];
            float4 b4 = *(const float4*)&Bs[k][tx * 4];
            float a[4] = {a4.x, a4.y, a4.z, a4.w};
            float b[4] = {b4.x, b4.y, b4.z, b4.w};
#pragma unroll
            for (int r = 0; r < 4; r++)
#pragma unroll
                for (int c = 0; c < 4; c++) acc[r][c] = fmaf(a[r], b[c], acc[r][c]);
        }
        __syncthreads();
    }
#pragma unroll
    for (int r = 0; r < 4; r++) {
        float4 o = {acc[r][0], acc[r][1], acc[r][2], acc[r][3]};
        *(float4*)&g_h[(size_t)(bm + ty * 4 + r) * FOUT + bn + tx * 4] = o;
    }
}

// ---------------------------------------------------------------------------
// Kernel 2: s_src / s_dst
// ---------------------------------------------------------------------------
__global__ __launch_bounds__(256) void k_scores(const float* __restrict__ A)
{
    const int row = blockIdx.x * 8 + (threadIdx.x >> 5);
    const int lane = threadIdx.x & 31;
    const float4* h4 = (const float4*)(g_h + (size_t)row * FOUT);
    const float4* a14 = (const float4*)A;
    const float4* a24 = (const float4*)(A + FOUT);
    float s1 = 0.f, s2 = 0.f;
#pragma unroll
    for (int i = 0; i < 2; i++) {
        int idx = lane + i * 32;
        float4 h = h4[idx], a1 = a14[idx], a2 = a24[idx];
        s1 += h.x * a1.x + h.y * a1.y + h.z * a1.z + h.w * a1.w;
        s2 += h.x * a2.x + h.y * a2.y + h.z * a2.z + h.w * a2.w;
    }
#pragma unroll
    for (int off = 16; off; off >>= 1) {
        s1 += __shfl_down_sync(0xffffffffu, s1, off);
        s2 += __shfl_down_sync(0xffffffffu, s2, off);
    }
    if (lane == 0) { g_s[row] = s1; g_s[N_NODES + row] = s2; }
}

// ---------------------------------------------------------------------------
// Kernel 3: h -> h^T split into bf16 hi + residual lo
// ---------------------------------------------------------------------------
__global__ __launch_bounds__(256) void k_hsplit()
{
    __shared__ float t[32][33];
    const int tid = threadIdx.x, tx = tid & 31, ty = tid >> 5;
    const int ibase = blockIdx.x * 32, nbase = blockIdx.y * 32;
#pragma unroll
    for (int r = 0; r < 4; r++)
        t[ty + r * 8][tx] = g_h[(size_t)(ibase + ty + r * 8) * FOUT + nbase + tx];
    __syncthreads();
#pragma unroll
    for (int r = 0; r < 4; r++) {
        int nl = ty + r * 8;
        float v = t[tx][nl];
        __nv_bfloat16 hi = __float2bfloat16(v);
        __nv_bfloat16 lo = __float2bfloat16(v - __bfloat162float(hi));
        size_t o = (size_t)(nbase + nl) * N_NODES + ibase + tx;
        g_hT_hi[o] = hi;
        g_hT_lo[o] = lo;
    }
}

// ---------------------------------------------------------------------------
// Kernel 4: attention via mma.sync bf16 with 3-term split compensation.
// Grid (64, NSPLIT). CTA: M=128 i-rows, N=256, K = 4096 j.  8 warps, each 64x64.
// SMEM stage: A(w) [128m x 64k] hi+lo (32KB) + B(h^T) [256n x 64k] hi+lo (64KB)
// ---------------------------------------------------------------------------
#define ST_SZ  98304
#define A_HI(s) ((s) * ST_SZ)
#define A_LO(s) ((s) * ST_SZ + 16384)
#define B_HI(s) ((s) * ST_SZ + 32768)
#define B_LO(s) ((s) * ST_SZ + 65536)
#define ATTN_SMEM (2 * ST_SZ)   // 196608

__global__ __launch_bounds__(256, 1) void k_gat_attn_mma(const int* __restrict__ adj)
{
    extern __shared__ char smem[];
    __shared__ float sden[256];
    const uint32_t sb = smem_u32(smem);
    const int tid = threadIdx.x;
    const int lane = tid & 31;
    const int wid = tid >> 5;

    const int row0 = blockIdx.x * 128;
    const int half = blockIdx.y;
    const int jbase = half * KHALF;

    // producer mapping: 2 threads per i-row, 32 j each
    const int r  = tid & 127;
    const int kg = tid >> 7;
    const float my_ssrc = g_s[row0 + r];
    const float* __restrict__ sdst = g_s + N_NODES;
    const int* __restrict__ adjrow = adj + (size_t)(row0 + r) * N_NODES;
    const char* __restrict__ bhi_src = (const char*)(g_hT_hi + (size_t)tid * N_NODES + jbase);
    const char* __restrict__ blo_src = (const char*)(g_hT_lo + (size_t)tid * N_NODES + jbase);

    // consumer mapping: warp (warp_m, warp_n) owns 64x64 of the 128x256 tile
    const int warp_m = wid & 1;
    const int warp_n = wid >> 1;
    const uint32_t arow_base = (uint32_t)(warp_m * 64 + (lane & 15)) * 128;
    const int ksw = lane & 7;            // swizzle xor (row&7) for both A and B
    const int alsel = lane >> 4;         // A chunk select per lane

    float acc[4][8][4];
#pragma unroll
    for (int mt = 0; mt < 4; mt++)
#pragma unroll
        for (int nt = 0; nt < 8; nt++)
#pragma unroll
            for (int q = 0; q < 4; q++) acc[mt][nt][q] = 0.f;
    float psum = 0.f;

    // ---- producer lambda-ish macro ----
#define PRODUCE(c_, st_)                                                         \
    {                                                                            \
        const int j0 = jbase + (c_) * BKC;                                       \
        const int4*   ap = (const int4*)(adjrow + j0 + kg * 32);                 \
        const float4* sp = (const float4*)(sdst + j0 + kg * 32);                 \
        const uint32_t abase = (uint32_t)r * 128 + kg * 64;                      \
        _Pragma("unroll")                                                        \
        for (int q = 0; q < 8; q++) {                                            \
            int4   av = __ldg(ap + q);                                           \
            float4 sv = __ldg(sp + q);                                           \
            float w0 = (av.x > 0) ? __expf(fast_mish(my_ssrc + sv.x)) : 0.f;     \
            float w1 = (av.y > 0) ? __expf(fast_mish(my_ssrc + sv.y)) : 0.f;     \
            float w2 = (av.z > 0) ? __expf(fast_mish(my_ssrc + sv.z)) : 0.f;     \
            float w3 = (av.w > 0) ? __expf(fast_mish(my_ssrc + sv.w)) : 0.f;     \
            psum += (w0 + w1) + (w2 + w3);                                       \
            uint32_t h01 = pack_bf16(w0, w1), h23 = pack_bf16(w2, w3);           \
            float r0 = w0 - __bfloat162float(__float2bfloat16(w0));              \
            float r1 = w1 - __bfloat162float(__float2bfloat16(w1));              \
            float r2 = w2 - __bfloat162float(__float2bfloat16(w2));              \
            float r3 = w3 - __bfloat162float(__float2bfloat16(w3));              \
            uint32_t l01 = pack_bf16(r0, r1), l23 = pack_bf16(r2, r3);           \
            uint32_t bo = SW128(abase + q * 8);                                  \
            *(uint64_t*)(smem + A_HI(st_) + bo) = (uint64_t)h01 | ((uint64_t)h23 << 32); \
            *(uint64_t*)(smem + A_LO(st_) + bo) = (uint64_t)l01 | ((uint64_t)l23 << 32); \
        }                                                                        \
        const uint32_t bb = (uint32_t)tid * 128;                                 \
        const size_t gsrc = (size_t)(c_) * (BKC * 2);                            \
        _Pragma("unroll")                                                        \
        for (int t = 0; t < 8; t++) {                                            \
            uint32_t so = SW128(bb + t * 16);                                    \
            cpa16(sb + B_HI(st_) + so, bhi_src + gsrc + t * 16);                 \
            cpa16(sb + B_LO(st_) + so, blo_src + gsrc + t * 16);                 \
        }                                                                        \
        CPA_COMMIT();                                                            \
    }

    PRODUCE(0, 0);

    for (int c = 0; c < NCHUNK; c++) {
        const int st = c & 1;
        __syncthreads();   // consume(c-1) done before overwriting stage (c+1)&1
        if (c + 1 < NCHUNK) {
            PRODUCE(c + 1, (c + 1) & 1);
            CPA_WAIT(1);
        } else {
            CPA_WAIT(0);
        }
        __syncthreads();   // stage c (A STS + B cp.async) visible to all

        // ---- consume stage st: 4 k16 slices ----
#pragma unroll
        for (int ks = 0; ks < 4; ks++) {
            uint32_t Ah[4][4], Al[4][4];
            const int kcA = ks * 2 + alsel;
#pragma unroll
            for (int mt = 0; mt < 4; mt++) {
                uint32_t addr = sb + A_HI(st) + arow_base + mt * 2048 +
                                (uint32_t)((kcA ^ ksw) << 4);
                ldsm4(Ah[mt], addr);
                ldsm4(Al[mt], addr + 16384);
            }
#pragma unroll
            for (int ng = 0; ng < 4; ng++) {
                const int g = lane >> 3;
                const int brow = warp_n * 64 + ng * 16 + (lane & 7) + ((g & 2) << 2);
                const int kcB = ks * 2 + (g & 1);
                uint32_t baddr = sb + B_HI(st) + (uint32_t)brow * 128 +
                                 (uint32_t)((kcB ^ ksw) << 4);
                uint32_t Bh[4], Bl[4];
                ldsm4(Bh, baddr);
                ldsm4(Bl, baddr + 32768);
#pragma unroll
                for (int mt = 0; mt < 4; mt++) {
                    mma_bf16(acc[mt][ng * 2],     Ah[mt], Bh[0], Bh[1]);
                    mma_bf16(acc[mt][ng * 2 + 1], Ah[mt], Bh[2], Bh[3]);
                    mma_bf16(acc[mt][ng * 2],     Ah[mt], Bl[0], Bl[1]);
                    mma_bf16(acc[mt][ng * 2 + 1], Ah[mt], Bl[2], Bl[3]);
                    mma_bf16(acc[mt][ng * 2],     Al[mt], Bh[0], Bh[1]);
                    mma_bf16(acc[mt][ng * 2 + 1], Al[mt], Bh[2], Bh[3]);
                }
            }
        }
    }

    // ---- denominators ----
    sden[tid] = psum;
    __syncthreads();
    if (tid < 128)
        g_pden[half * N_NODES + row0 + tid] = sden[tid] + sden[tid + 128];

    // ---- numerators: mma d-frag layout -> g_pnum ----
    float* base = g_pnum + (size_t)half * N_NODES * FOUT;
#pragma unroll
    for (int mt = 0; mt < 4; mt++) {
#pragma unroll
        for (int nt = 0; nt < 8; nt++) {
            int row = row0 + warp_m * 64 + mt * 16 + (lane >> 2);
            int col = warp_n * 64 + nt * 8 + (lane & 3) * 2;
            float2 v0 = {acc[mt][nt][0], acc[mt][nt][1]};
            float2 v1 = {acc[mt][nt][2], acc[mt][nt][3]};
            *(float2*)&base[(size_t)row * FOUT + col] = v0;
            *(float2*)&base[(size_t)(row + 8) * FOUT + col] = v1;
        }
    }
#undef PRODUCE
}

// ---------------------------------------------------------------------------
// Kernel 5: combine K-split partials + final mish
// ---------------------------------------------------------------------------
__global__ __launch_bounds__(256) void k_combine(float* __restrict__ out)
{
    const int idx = blockIdx.x * 256 + threadIdx.x;
    const int row = idx >> 6;
    const float4* p0 = (const float4*)g_pnum;
    const float4* p1 = (const float4*)(g_pnum + (size_t)N_NODES * FOUT);
    float inv = __fdividef(1.f, g_pden[row] + g_pden[N_NODES + row]);
    float4 a = p0[idx], b = p1[idx];
    float4 o;
    o.x = fast_mish((a.x + b.x) * inv);
    o.y = fast_mish((a.y + b.y) * inv);
    o.z = fast_mish((a.z + b.z) * inv);
    o.w = fast_mish((a.w + b.w) * inv);
    ((float4*)out)[idx] = o;
}

// ---------------------------------------------------------------------------
extern "C" void kernel_launch(void* const* d_in, const int* in_sizes, int n_in,
                              void* d_out, int out_size)
{
    const float* x   = (const float*)d_in[0];   // [8192, 512]
    const int*   adj = (const int*)  d_in[1];   // [8192, 8192]
    const float* w   = (const float*)d_in[2];   // [512, 256]
    const float* a   = (const float*)d_in[3];   // [512, 1]
    float* out = (float*)d_out;                 // [8192, 256]

    cudaFuncSetAttribute(k_gat_attn_mma, cudaFuncAttributeMaxDynamicSharedMemorySize,
                         ATTN_SMEM);

    k_sgemm_xw<<<dim3(FOUT / 64, N_NODES / 64), 256>>>(x, w);
    k_scores<<<N_NODES / 8, 256>>>(a);
    k_hsplit<<<dim3(N_NODES / 32, FOUT / 32), 256>>>();
    k_gat_attn_mma<<<dim3(N_NODES / 128, NSPLIT), 256, ATTN_SMEM>>>(adj);
    k_combine<<<(N_NODES * FOUT / 4) / 256, 256>>>(out);
}